// round 6
// baseline (speedup 1.0000x reference)
#include <cuda_runtime.h>
#include <cuda_fp16.h>
#include <cstdint>

#define NMAX 100000
#define EMAX 1601000
#define HEADS 8
#define F 128
#define NEG_SLOPE 0.2f

// ---------------- static scratch (no allocation) ----------------
__device__ __align__(16) __half g_h[(size_t)NMAX * F];   // 25.6 MB (fp16)
__device__ __align__(16) float g_asrc[NMAX * HEADS];
__device__ __align__(16) float g_adst[NMAX * HEADS];
__device__ int g_cnt[NMAX];
__device__ int g_start[NMAX];
__device__ int g_cursor[NMAX];
__device__ int g_esrc[EMAX];
__device__ int g_bsum[128];
__device__ int g_idx64;

// ---------------- init: zero counts + parallel dtype sniff ----------------
__global__ void init_kernel(const long long* __restrict__ ei, long long E, int nodes) {
    int i = blockIdx.x * blockDim.x + threadIdx.x;
    if (i < nodes) g_cnt[i] = 0;
    if (blockIdx.x == 0 && threadIdx.x < 32) {
        long long stride = E / 32;
        if (stride < 1) stride = 1;
        long long v = ei[stride * threadIdx.x];
        unsigned bad = __ballot_sync(0xffffffffu, v < 0 || v >= NMAX);
        if (threadIdx.x == 0) g_idx64 = (bad == 0u);
    }
}

// ---------------- node transform: h = xW (fp16 out), attention scalars ----------------
__global__ void __launch_bounds__(128) node_kernel(
    const float* __restrict__ x, const float* __restrict__ W,
    const float* __restrict__ att_src, const float* __restrict__ att_dst,
    int nodes)
{
    __shared__ float sW[16 * F];
    __shared__ float sx[32][16];
    const int t = threadIdx.x;
    for (int i = t; i < 16 * F; i += 128) sW[i] = W[i];

    const int base = blockIdx.x * 32;
    const int nrem = min(32, nodes - base);
    if (t < (nrem * 16) / 4)
        ((float4*)&sx[0][0])[t] = ((const float4*)(x + (size_t)base * 16))[t];
    __syncthreads();

    const int head = t >> 4;
    const int c    = t & 15;
    const float as = att_src[t];
    const float ad = att_dst[t];

    for (int nn = 0; nn < nrem; nn++) {
        const int n = base + nn;
        float hj = 0.f;
        #pragma unroll
        for (int k = 0; k < 16; k++)
            hj = fmaf(sx[nn][k], sW[k * F + t], hj);

        float s1 = hj * as, s2 = hj * ad;
        #pragma unroll
        for (int off = 8; off; off >>= 1) {
            s1 += __shfl_xor_sync(0xffffffffu, s1, off, 16);
            s2 += __shfl_xor_sync(0xffffffffu, s2, off, 16);
        }
        float hn = __shfl_down_sync(0xffffffffu, hj, 1);
        if ((t & 1) == 0)
            *(__half2*)&g_h[(size_t)n * F + t] = __floats2half2_rn(hj, hn);
        if (c == 0) {
            g_asrc[n * HEADS + head] = s1;
            g_adst[n * HEADS + head] = s2;
        }
    }
}

// ---------------- CSR build ----------------
__global__ void hist_kernel(const long long* __restrict__ ei64,
                            const int* __restrict__ ei32, long long E) {
    const long long base = (long long)blockIdx.x * 1024 + threadIdx.x;
    const int use64 = g_idx64;
    #pragma unroll
    for (int i = 0; i < 4; i++) {
        long long e = base + i * 256;
        if (e < E) {
            int dst = use64 ? (int)ei64[E + e] : ei32[E + e];
            atomicAdd(&g_cnt[dst], 1);
        }
    }
}

__global__ void scanA_kernel(int nodes) {
    __shared__ int sh[256];
    int t = threadIdx.x, b = blockIdx.x;
    int base = (b * 256 + t) * 4;
    int s = 0;
    #pragma unroll
    for (int i = 0; i < 4; i++) { int j = base + i; if (j < nodes) s += g_cnt[j]; }
    sh[t] = s; __syncthreads();
    for (int off = 128; off; off >>= 1) {
        if (t < off) sh[t] += sh[t + off];
        __syncthreads();
    }
    if (t == 0) g_bsum[b] = sh[0];
}

// fused scanB+scanC: each block redundantly scans the 128 block sums
__global__ void scanC_kernel(int nodes) {
    __shared__ int sbs[128];
    __shared__ int sh[256];
    int t = threadIdx.x, b = blockIdx.x;
    if (t < 128) sbs[t] = g_bsum[t];
    __syncthreads();
    for (int off = 1; off < 128; off <<= 1) {
        int v = (t >= off && t < 128) ? sbs[t - off] : 0;
        __syncthreads();
        if (t < 128) sbs[t] += v;
        __syncthreads();
    }
    const int blockbase = (b > 0) ? sbs[b - 1] : 0;

    int base = (b * 256 + t) * 4;
    int c[4]; int s = 0;
    #pragma unroll
    for (int i = 0; i < 4; i++) {
        c[i] = (base + i < nodes) ? g_cnt[base + i] : 0;
        s += c[i];
    }
    sh[t] = s; __syncthreads();
    for (int off = 1; off < 256; off <<= 1) {
        int v = (t >= off) ? sh[t - off] : 0;
        __syncthreads();
        sh[t] += v;
        __syncthreads();
    }
    int run = blockbase + sh[t] - s;
    #pragma unroll
    for (int i = 0; i < 4; i++) {
        if (base + i < nodes) {
            g_start[base + i]  = run;
            g_cursor[base + i] = run;
            run += c[i];
        }
    }
}

__global__ void scatter_kernel(const long long* __restrict__ ei64,
                               const int* __restrict__ ei32, long long E) {
    const long long base = (long long)blockIdx.x * 512 + threadIdx.x;
    const int use64 = g_idx64;
    #pragma unroll
    for (int i = 0; i < 2; i++) {
        long long e = base + i * 256;
        if (e < E) {
            int src, dst;
            if (use64) { src = (int)ei64[e]; dst = (int)ei64[E + e]; }
            else       { src = ei32[e];      dst = ei32[E + e]; }
            int pos = atomicAdd(&g_cursor[dst], 1);
            g_esrc[pos] = src;
        }
    }
}

// ---------------- gather + finalize fused (1 warp / node) ----------------
// lane l: h = l>>2, feature chunk j0 = l*4. Exp work distributed: lane l
// computes the weight for (edge e+(l&3), head l>>2); weights shared via shfl.
__global__ void __launch_bounds__(256) gather_kernel(
    const float* __restrict__ bias, const float* __restrict__ fc_w,
    const float* __restrict__ fc_b, float* __restrict__ out, int nodes)
{
    __shared__ float sb[F];
    __shared__ float sw[5][F];
    __shared__ float sfb[5];
    const int t = threadIdx.x;
    for (int i = t; i < F; i += 256) sb[i] = bias[i];
    for (int i = t; i < 5 * F; i += 256) { int j = i / 5, k = i % 5; sw[k][j] = fc_w[i]; }
    if (t < 5) sfb[t] = fc_b[t];
    __syncthreads();

    const int n = blockIdx.x * 8 + (t >> 5);
    if (n >= nodes) return;
    const int lane = t & 31;
    const int h = lane >> 2;
    const int eh = lane & 3;     // this lane's exp-edge slot within a 4-group
    const int hb = lane & ~3;    // base lane of this head's 4-lane group
    const int j0 = lane * 4;

    const float adw = g_adst[n * HEADS + h];

    // self loop (exp redundant across the 4 head-lanes; once per node, fine)
    float a = g_asrc[n * HEADS + h] + adw;
    a = fmaxf(a, NEG_SLOPE * a);
    float w = __expf(a);
    {
        uint2 r = *(const uint2*)&g_h[(size_t)n * F + j0];
        float2 lo = __half22float2(*(__half2*)&r.x);
        float2 hi = __half22float2(*(__half2*)&r.y);
        // init accumulators
        float dsum = w;
        float ax = w * lo.x, ay = w * lo.y, az = w * hi.x, aw_ = w * hi.y;

        const int s0 = g_start[n];
        const int end = s0 + g_cnt[n];

        for (int e = s0; e < end; e += 8) {
            // ---- group A: edges e..e+3 ----
            int eA = e + eh;
            int iA0 = (e + 0 < end) ? __ldg(&g_esrc[e + 0]) : 0;
            int iA1 = (e + 1 < end) ? __ldg(&g_esrc[e + 1]) : 0;
            int iA2 = (e + 2 < end) ? __ldg(&g_esrc[e + 2]) : 0;
            int iA3 = (e + 3 < end) ? __ldg(&g_esrc[e + 3]) : 0;
            // ---- group B: edges e+4..e+7 ----
            int eB = e + 4 + eh;
            int iB0 = (e + 4 < end) ? __ldg(&g_esrc[e + 4]) : 0;
            int iB1 = (e + 5 < end) ? __ldg(&g_esrc[e + 5]) : 0;
            int iB2 = (e + 6 < end) ? __ldg(&g_esrc[e + 6]) : 0;
            int iB3 = (e + 7 < end) ? __ldg(&g_esrc[e + 7]) : 0;

            int idxA = (eh == 0) ? iA0 : (eh == 1) ? iA1 : (eh == 2) ? iA2 : iA3;
            int idxB = (eh == 0) ? iB0 : (eh == 1) ? iB1 : (eh == 2) ? iB2 : iB3;

            float aA = g_asrc[idxA * HEADS + h] + adw;
            float aB = g_asrc[idxB * HEADS + h] + adw;

            uint2 rA0 = *(const uint2*)&g_h[(size_t)iA0 * F + j0];
            uint2 rA1 = *(const uint2*)&g_h[(size_t)iA1 * F + j0];
            uint2 rA2 = *(const uint2*)&g_h[(size_t)iA2 * F + j0];
            uint2 rA3 = *(const uint2*)&g_h[(size_t)iA3 * F + j0];
            uint2 rB0 = *(const uint2*)&g_h[(size_t)iB0 * F + j0];
            uint2 rB1 = *(const uint2*)&g_h[(size_t)iB1 * F + j0];
            uint2 rB2 = *(const uint2*)&g_h[(size_t)iB2 * F + j0];
            uint2 rB3 = *(const uint2*)&g_h[(size_t)iB3 * F + j0];

            aA = fmaxf(aA, NEG_SLOPE * aA);
            aB = fmaxf(aB, NEG_SLOPE * aB);
            float wA = (eA < end) ? __expf(aA) : 0.f;
            float wB = (eB < end) ? __expf(aB) : 0.f;

            float w0 = __shfl_sync(0xffffffffu, wA, hb | 0);
            float w1 = __shfl_sync(0xffffffffu, wA, hb | 1);
            float w2 = __shfl_sync(0xffffffffu, wA, hb | 2);
            float w3 = __shfl_sync(0xffffffffu, wA, hb | 3);
            float w4 = __shfl_sync(0xffffffffu, wB, hb | 0);
            float w5 = __shfl_sync(0xffffffffu, wB, hb | 1);
            float w6 = __shfl_sync(0xffffffffu, wB, hb | 2);
            float w7 = __shfl_sync(0xffffffffu, wB, hb | 3);

            dsum += ((w0 + w1) + (w2 + w3)) + ((w4 + w5) + (w6 + w7));

            float2 l0 = __half22float2(*(__half2*)&rA0.x), u0 = __half22float2(*(__half2*)&rA0.y);
            float2 l1 = __half22float2(*(__half2*)&rA1.x), u1 = __half22float2(*(__half2*)&rA1.y);
            float2 l2 = __half22float2(*(__half2*)&rA2.x), u2 = __half22float2(*(__half2*)&rA2.y);
            float2 l3 = __half22float2(*(__half2*)&rA3.x), u3 = __half22float2(*(__half2*)&rA3.y);
            float2 l4 = __half22float2(*(__half2*)&rB0.x), u4 = __half22float2(*(__half2*)&rB0.y);
            float2 l5 = __half22float2(*(__half2*)&rB1.x), u5 = __half22float2(*(__half2*)&rB1.y);
            float2 l6 = __half22float2(*(__half2*)&rB2.x), u6 = __half22float2(*(__half2*)&rB2.y);
            float2 l7 = __half22float2(*(__half2*)&rB3.x), u7 = __half22float2(*(__half2*)&rB3.y);

            ax += (w0 * l0.x + w1 * l1.x + w2 * l2.x + w3 * l3.x)
                + (w4 * l4.x + w5 * l5.x + w6 * l6.x + w7 * l7.x);
            ay += (w0 * l0.y + w1 * l1.y + w2 * l2.y + w3 * l3.y)
                + (w4 * l4.y + w5 * l5.y + w6 * l6.y + w7 * l7.y);
            az += (w0 * u0.x + w1 * u1.x + w2 * u2.x + w3 * u3.x)
                + (w4 * u4.x + w5 * u5.x + w6 * u6.x + w7 * u7.x);
            aw_ += (w0 * u0.y + w1 * u1.y + w2 * u2.y + w3 * u3.y)
                 + (w4 * u4.y + w5 * u5.y + w6 * u6.y + w7 * u7.y);
        }

        const float inv = 1.f / (dsum + 1e-16f);
        float o0 = fmaxf(fmaf(ax, inv, sb[j0 + 0]), 0.f);
        float o1 = fmaxf(fmaf(ay, inv, sb[j0 + 1]), 0.f);
        float o2 = fmaxf(fmaf(az, inv, sb[j0 + 2]), 0.f);
        float o3 = fmaxf(fmaf(aw_, inv, sb[j0 + 3]), 0.f);

        float p[5];
        #pragma unroll
        for (int k = 0; k < 5; k++) {
            p[k] = o0 * sw[k][j0 + 0] + o1 * sw[k][j0 + 1]
                 + o2 * sw[k][j0 + 2] + o3 * sw[k][j0 + 3];
        }
        #pragma unroll
        for (int off = 16; off; off >>= 1) {
            #pragma unroll
            for (int k = 0; k < 5; k++)
                p[k] += __shfl_xor_sync(0xffffffffu, p[k], off);
        }
        if (lane == 0) {
            #pragma unroll
            for (int k = 0; k < 5; k++) p[k] += sfb[k];
            float m = p[0];
            #pragma unroll
            for (int k = 1; k < 5; k++) m = fmaxf(m, p[k]);
            float s = 0.f;
            #pragma unroll
            for (int k = 0; k < 5; k++) s += __expf(p[k] - m);
            const float lse = m + logf(s);
            #pragma unroll
            for (int k = 0; k < 5; k++)
                out[(size_t)n * 5 + k] = p[k] - lse;
        }
    }
}

// ---------------- launch ----------------
extern "C" void kernel_launch(void* const* d_in, const int* in_sizes, int n_in,
                              void* d_out, int out_size)
{
    const float* x       = (const float*)d_in[0];
    const void*  ei      = d_in[1];
    const float* W       = (const float*)d_in[2];
    const float* att_src = (const float*)d_in[3];
    const float* att_dst = (const float*)d_in[4];
    const float* bias    = (const float*)d_in[5];
    const float* fc_w    = (const float*)d_in[6];
    const float* fc_b    = (const float*)d_in[7];
    float* out = (float*)d_out;

    const int nodes = in_sizes[0] / 16;
    const long long E = (long long)in_sizes[1] / 2;

    init_kernel<<<(nodes + 255) / 256, 256>>>((const long long*)ei, E, nodes);
    node_kernel<<<(nodes + 31) / 32, 128>>>(x, W, att_src, att_dst, nodes);

    hist_kernel<<<(int)((E + 1023) / 1024), 256>>>((const long long*)ei, (const int*)ei, E);
    scanA_kernel<<<128, 256>>>(nodes);
    scanC_kernel<<<128, 256>>>(nodes);
    scatter_kernel<<<(int)((E + 511) / 512), 256>>>((const long long*)ei, (const int*)ei, E);

    gather_kernel<<<(nodes + 7) / 8, 256>>>(bias, fc_w, fc_b, out, nodes);
}